// round 3
// baseline (speedup 1.0000x reference)
#include <cuda_runtime.h>
#include <cuda_fp16.h>
#include <math.h>

#define Bb 32
#define Nn 512
#define Mm 512
#define EPSV 0.05f
#define NITERS 50
#define NEGC (-1e9f)

// Scratch (device globals: allocation-free per harness rules)
// K stored fp16: halves lse-pass traffic (memory-bound kernel).
__device__ __half g_Kh [(size_t)Bb * Nn * Mm];   // logK row-major   [b][i][j]
__device__ __half g_KTh[(size_t)Bb * Mm * Nn];   // logK transposed  [b][j][i]
__device__ float g_loga[Bb * Nn];
__device__ float g_logb[Bb * Mm];
__device__ float g_logu[Bb * Nn];
__device__ float g_logv[Bb * Mm];

// ---------------------------------------------------------------------------
// prep: per-batch masses, log-weights, logv init, huber term into out[b]
// grid = B, block = 512
__global__ void prep_kernel(const float* __restrict__ a_mask,
                            const float* __restrict__ pc_a,
                            const float* __restrict__ b_mask,
                            const float* __restrict__ pc_b,
                            float* __restrict__ out)
{
    int b = blockIdx.x, t = threadIdx.x;
    float apt = a_mask[b * Nn + t] * pc_a[(b * Nn + t) * 3 + 2];
    float bpt = b_mask[b * Mm + t] * pc_b[(b * Mm + t) * 3 + 2];

    __shared__ float ra[512], rb[512];
    ra[t] = apt; rb[t] = bpt;
    __syncthreads();
    for (int o = 256; o; o >>= 1) {
        if (t < o) { ra[t] += ra[t + o]; rb[t] += rb[t + o]; }
        __syncthreads();
    }
    float sa = ra[0], sb = rb[0];

    g_loga[b * Nn + t] = (apt > 0.f) ? logf(apt / sa) : NEGC;
    g_logb[b * Mm + t] = (bpt > 0.f) ? logf(bpt / sb) : NEGC;
    g_logv[b * Mm + t] = 0.f;   // reference starts logv = 0

    if (t == 0) {
        float e = sa - sb;
        float ae = fabsf(e);
        out[b] = (ae <= 1.f) ? 0.5f * e * e : (ae - 0.5f);
    }
}

// ---------------------------------------------------------------------------
// build logK and logK^T (fp16).  grid = (M/32, N/32, B), block = (32, 32)
__global__ void computeK_kernel(const float* __restrict__ a_mask,
                                const float* __restrict__ pc_a,
                                const float* __restrict__ b_mask,
                                const float* __restrict__ pc_b)
{
    int b  = blockIdx.z;
    int i0 = blockIdx.y * 32, j0 = blockIdx.x * 32;
    int tx = threadIdx.x, ty = threadIdx.y;

    __shared__ float ax[32], ay[32], av[32];
    __shared__ float bx[32], by[32], bv[32];
    __shared__ __half tile[32][33];

    if (ty == 0) {
        int i = i0 + tx; int base = (b * Nn + i) * 3;
        ax[tx] = pc_a[base + 0];
        ay[tx] = pc_a[base + 1];
        av[tx] = (a_mask[b * Nn + i] * pc_a[base + 2] > 0.f) ? 1.f : 0.f;
    } else if (ty == 1) {
        int j = j0 + tx; int base = (b * Mm + j) * 3;
        bx[tx] = pc_b[base + 0];
        by[tx] = pc_b[base + 1];
        bv[tx] = (b_mask[b * Mm + j] * pc_b[base + 2] > 0.f) ? 1.f : 0.f;
    }
    __syncthreads();

    float dx = ax[ty] - bx[tx];
    float dy = ay[ty] - by[tx];
    float d  = sqrtf(dx * dx + dy * dy + 1e-12f);
    float val = (av[ty] * bv[tx] > 0.f) ? (-d * (1.f / EPSV)) : 0.f;
    __half hv = __float2half(val);

    g_Kh[((size_t)(b * Nn + (i0 + ty))) * Mm + (j0 + tx)] = hv;
    tile[ty][tx] = hv;
    __syncthreads();
    g_KTh[((size_t)(b * Mm + (j0 + ty))) * Nn + (i0 + tx)] = tile[tx][ty];
}

// ---------------------------------------------------------------------------
// one lse half-pass: dst[row] = w[row] - logsumexp_j( K[row][j] + src[j] )
// warp-per-row; row = 512 fp16 loaded as 2 x uint4 (16B) per lane,
// 1 exp per element, two-pass (max then sum) in registers.
// grid = B*512/8, block = 256 (8 warps)
template <bool UPASS>
__global__ void lse_kernel()
{
    const __half* __restrict__ K  = UPASS ? g_Kh   : g_KTh;
    const float* __restrict__ src = UPASS ? g_logv : g_logu;
    const float* __restrict__ w   = UPASS ? g_loga : g_logb;
    float*       __restrict__ dst = UPASS ? g_logu : g_logv;

    __shared__ float sv[512];
    int b    = blockIdx.x >> 6;          // 64 blocks per batch
    int row0 = (blockIdx.x & 63) * 8;

    for (int t = threadIdx.x; t < 512; t += 256)
        sv[t] = src[b * 512 + t];
    __syncthreads();

    int warp = threadIdx.x >> 5, lane = threadIdx.x & 31;
    int i = row0 + warp;
    const __half* Kr = K + ((size_t)(b * 512 + i)) * 512;
    const float4* sv4 = (const float4*)sv;

    // lane owns cols [lane*8 .. lane*8+7] and [256+lane*8 .. 256+lane*8+7]
    float x[16];
    float m = -3.4e38f;
#pragma unroll
    for (int h = 0; h < 2; h++) {
        uint4 kv = ((const uint4*)(Kr + h * 256))[lane];
        float4 s0 = sv4[h * 64 + lane * 2 + 0];
        float4 s1 = sv4[h * 64 + lane * 2 + 1];
        float2 p0 = __half22float2(*(const __half2*)&kv.x);
        float2 p1 = __half22float2(*(const __half2*)&kv.y);
        float2 p2 = __half22float2(*(const __half2*)&kv.z);
        float2 p3 = __half22float2(*(const __half2*)&kv.w);
        int o = h * 8;
        x[o + 0] = p0.x + s0.x;  x[o + 1] = p0.y + s0.y;
        x[o + 2] = p1.x + s0.z;  x[o + 3] = p1.y + s0.w;
        x[o + 4] = p2.x + s1.x;  x[o + 5] = p2.y + s1.y;
        x[o + 6] = p3.x + s1.z;  x[o + 7] = p3.y + s1.w;
    }
#pragma unroll
    for (int k = 0; k < 16; k++) m = fmaxf(m, x[k]);
#pragma unroll
    for (int o = 16; o; o >>= 1) m = fmaxf(m, __shfl_xor_sync(0xFFFFFFFFu, m, o));

    float s = 0.f;
#pragma unroll
    for (int k = 0; k < 16; k++) s += __expf(x[k] - m);
#pragma unroll
    for (int o = 16; o; o >>= 1) s += __shfl_xor_sync(0xFFFFFFFFu, s, o);

    if (lane == 0)
        dst[b * 512 + i] = w[b * 512 + i] - (m + __logf(s));
}

// ---------------------------------------------------------------------------
// final: out[b] += sum_ij dist^2 * exp(logu + logK + logv), dist = -EPS*logK
// grid = B, block = 512 (thread t owns 2 adjacent columns via half2)
__global__ void final_kernel(float* __restrict__ out)
{
    int b = blockIdx.x, t = threadIdx.x;
    __shared__ float sv[512];
    __shared__ float red[512];
    sv[t] = g_logv[b * 512 + t];
    __syncthreads();

    // thread t owns columns 2t, 2t+1 -> only threads 0..255 do column work
    float acc = 0.f;
    if (t < 256) {
        const __half2* Kb2 = (const __half2*)(g_Kh + (size_t)b * 512 * 512);
        float v0 = sv[2 * t], v1 = sv[2 * t + 1];
        for (int i = 0; i < 512; i++) {
            float lu = g_logu[b * 512 + i];            // uniform -> broadcast
            float2 k = __half22float2(Kb2[(size_t)i * 256 + t]);
            acc += k.x * k.x * __expf(lu + k.x + v0)
                 + k.y * k.y * __expf(lu + k.y + v1);
        }
    }

    red[t] = acc;
    __syncthreads();
    for (int o = 256; o; o >>= 1) {
        if (t < o) red[t] += red[t + o];
        __syncthreads();
    }
    if (t == 0) out[b] += (EPSV * EPSV) * red[0];
}

// ---------------------------------------------------------------------------
extern "C" void kernel_launch(void* const* d_in, const int* in_sizes, int n_in,
                              void* d_out, int out_size)
{
    const float* a_mask = (const float*)d_in[0];
    const float* pc_a   = (const float*)d_in[1];
    const float* b_mask = (const float*)d_in[2];
    const float* pc_b   = (const float*)d_in[3];
    float* out = (float*)d_out;

    prep_kernel<<<Bb, 512>>>(a_mask, pc_a, b_mask, pc_b, out);
    computeK_kernel<<<dim3(Mm / 32, Nn / 32, Bb), dim3(32, 32)>>>(a_mask, pc_a, b_mask, pc_b);

    for (int it = 0; it < NITERS; ++it) {
        lse_kernel<true ><<<Bb * Nn / 8, 256>>>();   // logu update (reads Kh,  logv)
        lse_kernel<false><<<Bb * Mm / 8, 256>>>();   // logv update (reads KTh, logu)
    }

    final_kernel<<<Bb, 512>>>(out);
}

// round 4
// speedup vs baseline: 1.0910x; 1.0910x over previous
#include <cuda_runtime.h>
#include <cuda_fp16.h>
#include <math.h>

#define Bb 32
#define Nn 512
#define Mm 512
#define EPSV 0.05f
#define NITERS 50
#define NEGC (-1e9f)

#define NBLK 128           // persistent grid: 4 blocks per batch
#define NTHR 1024          // 32 warps; warp handles 4 rows per half-pass

// Scratch (device globals: allocation-free per harness rules)
__device__ __half g_Kh [(size_t)Bb * Nn * Mm];   // logK row-major   [b][i][j]
__device__ __half g_KTh[(size_t)Bb * Mm * Nn];   // logK transposed  [b][j][i]
__device__ float g_loga[Bb * Nn];
__device__ float g_logb[Bb * Mm];
__device__ float g_logu[Bb * Nn];
__device__ float g_logv[Bb * Mm];

// software grid barrier state (reset by prep_kernel each launch)
__device__ unsigned g_count;
__device__ volatile unsigned g_gen;

// ---------------------------------------------------------------------------
// prep: per-batch masses, log-weights, logv init, huber into out[b], bar reset
// grid = B, block = 512
__global__ void prep_kernel(const float* __restrict__ a_mask,
                            const float* __restrict__ pc_a,
                            const float* __restrict__ b_mask,
                            const float* __restrict__ pc_b,
                            float* __restrict__ out)
{
    int b = blockIdx.x, t = threadIdx.x;
    if (b == 0 && t == 0) { g_count = 0; g_gen = 0; }

    float apt = a_mask[b * Nn + t] * pc_a[(b * Nn + t) * 3 + 2];
    float bpt = b_mask[b * Mm + t] * pc_b[(b * Mm + t) * 3 + 2];

    __shared__ float ra[512], rb[512];
    ra[t] = apt; rb[t] = bpt;
    __syncthreads();
    for (int o = 256; o; o >>= 1) {
        if (t < o) { ra[t] += ra[t + o]; rb[t] += rb[t + o]; }
        __syncthreads();
    }
    float sa = ra[0], sb = rb[0];

    g_loga[b * Nn + t] = (apt > 0.f) ? logf(apt / sa) : NEGC;
    g_logb[b * Mm + t] = (bpt > 0.f) ? logf(bpt / sb) : NEGC;
    g_logv[b * Mm + t] = 0.f;   // reference starts logv = 0

    if (t == 0) {
        float e = sa - sb;
        float ae = fabsf(e);
        out[b] = (ae <= 1.f) ? 0.5f * e * e : (ae - 0.5f);
    }
}

// ---------------------------------------------------------------------------
// build logK and logK^T (fp16).  grid = (M/32, N/32, B), block = (32, 32)
__global__ void computeK_kernel(const float* __restrict__ a_mask,
                                const float* __restrict__ pc_a,
                                const float* __restrict__ b_mask,
                                const float* __restrict__ pc_b)
{
    int b  = blockIdx.z;
    int i0 = blockIdx.y * 32, j0 = blockIdx.x * 32;
    int tx = threadIdx.x, ty = threadIdx.y;

    __shared__ float ax[32], ay[32], av[32];
    __shared__ float bx[32], by[32], bv[32];
    __shared__ __half tile[32][33];

    if (ty == 0) {
        int i = i0 + tx; int base = (b * Nn + i) * 3;
        ax[tx] = pc_a[base + 0];
        ay[tx] = pc_a[base + 1];
        av[tx] = (a_mask[b * Nn + i] * pc_a[base + 2] > 0.f) ? 1.f : 0.f;
    } else if (ty == 1) {
        int j = j0 + tx; int base = (b * Mm + j) * 3;
        bx[tx] = pc_b[base + 0];
        by[tx] = pc_b[base + 1];
        bv[tx] = (b_mask[b * Mm + j] * pc_b[base + 2] > 0.f) ? 1.f : 0.f;
    }
    __syncthreads();

    float dx = ax[ty] - bx[tx];
    float dy = ay[ty] - by[tx];
    float d  = sqrtf(dx * dx + dy * dy + 1e-12f);
    float val = (av[ty] * bv[tx] > 0.f) ? (-d * (1.f / EPSV)) : 0.f;
    __half hv = __float2half(val);

    g_Kh[((size_t)(b * Nn + (i0 + ty))) * Mm + (j0 + tx)] = hv;
    tile[ty][tx] = hv;
    __syncthreads();
    g_KTh[((size_t)(b * Mm + (j0 + ty))) * Nn + (i0 + tx)] = tile[tx][ty];
}

// ---------------------------------------------------------------------------
// grid barrier: all NBLK blocks must be co-resident (NBLK <= 148, 1 blk/SM)
__device__ __forceinline__ void gsync(unsigned& gen)
{
    __syncthreads();
    if (threadIdx.x == 0) {
        __threadfence();                       // publish this block's dst stores
        unsigned arrived = atomicAdd(&g_count, 1u);
        if (arrived == NBLK - 1u) {
            g_count = 0;                       // safe: everyone has arrived
            __threadfence();
            g_gen = gen + 1u;                  // release (volatile -> L2)
        } else {
            while (g_gen < gen + 1u) { }       // spin on L2
        }
    }
    gen += 1u;
    __syncthreads();
}

// ---------------------------------------------------------------------------
// one lse half-pass over this block's 128 rows.
// dst[row] = w[row] - logsumexp_j( K[row][j] + src[j] )
template <bool UPASS>
__device__ __forceinline__ void half_pass(int batch, int row_base, float* sv)
{
    const __half* __restrict__ K  = UPASS ? g_Kh   : g_KTh;
    const float* __restrict__ src = UPASS ? g_logv : g_logu;
    const float* __restrict__ w   = UPASS ? g_loga : g_logb;
    float*       __restrict__ dst = UPASS ? g_logu : g_logv;

    // src written by other blocks: must bypass L1 (persistent kernel)
    if (threadIdx.x < 512)
        sv[threadIdx.x] = __ldcg(&src[batch * 512 + threadIdx.x]);
    __syncthreads();

    int warp = threadIdx.x >> 5, lane = threadIdx.x & 31;
    const float4* sv4 = (const float4*)sv;

#pragma unroll
    for (int r = 0; r < 4; r++) {
        int i = row_base + warp * 4 + r;
        const __half* Kr = K + ((size_t)(batch * 512 + i)) * 512;

        float x[16];
#pragma unroll
        for (int h = 0; h < 2; h++) {
            uint4 kv = ((const uint4*)(Kr + h * 256))[lane];
            float4 s0 = sv4[h * 64 + lane * 2 + 0];
            float4 s1 = sv4[h * 64 + lane * 2 + 1];
            float2 p0 = __half22float2(*(const __half2*)&kv.x);
            float2 p1 = __half22float2(*(const __half2*)&kv.y);
            float2 p2 = __half22float2(*(const __half2*)&kv.z);
            float2 p3 = __half22float2(*(const __half2*)&kv.w);
            int o = h * 8;
            x[o + 0] = p0.x + s0.x;  x[o + 1] = p0.y + s0.y;
            x[o + 2] = p1.x + s0.z;  x[o + 3] = p1.y + s0.w;
            x[o + 4] = p2.x + s1.x;  x[o + 5] = p2.y + s1.y;
            x[o + 6] = p3.x + s1.z;  x[o + 7] = p3.y + s1.w;
        }
        float m = x[0];
#pragma unroll
        for (int k = 1; k < 16; k++) m = fmaxf(m, x[k]);
#pragma unroll
        for (int o = 16; o; o >>= 1) m = fmaxf(m, __shfl_xor_sync(0xFFFFFFFFu, m, o));

        float s = 0.f;
#pragma unroll
        for (int k = 0; k < 16; k++) s += __expf(x[k] - m);
#pragma unroll
        for (int o = 16; o; o >>= 1) s += __shfl_xor_sync(0xFFFFFFFFu, s, o);

        if (lane == 0)
            dst[batch * 512 + i] = w[batch * 512 + i] - (m + __logf(s));
    }
}

// ---------------------------------------------------------------------------
// persistent Sinkhorn: all 50 iterations, grid barrier between half-passes.
// grid = NBLK(128) blocks, block = NTHR(1024). Block bid owns rows
// [ (bid&3)*128 .. +128 ) of batch bid>>2, in both K and KT.
__global__ void __launch_bounds__(NTHR, 1) sinkhorn_kernel()
{
    __shared__ float sv[512];
    int batch    = blockIdx.x >> 2;
    int row_base = (blockIdx.x & 3) * 128;
    unsigned gen = 0;

    for (int it = 0; it < NITERS; ++it) {
        half_pass<true >(batch, row_base, sv);   // logu update (reads Kh,  logv)
        gsync(gen);
        half_pass<false>(batch, row_base, sv);   // logv update (reads KTh, logu)
        if (it != NITERS - 1) gsync(gen);        // last sync via stream order
    }
}

// ---------------------------------------------------------------------------
// final: out[b] += sum_ij dist^2 * exp(logu + logK + logv), dist = -EPS*logK
// grid = B, block = 512 (threads 0..255 own 2 adjacent columns via half2)
__global__ void final_kernel(float* __restrict__ out)
{
    int b = blockIdx.x, t = threadIdx.x;
    __shared__ float sv[512];
    __shared__ float red[512];
    sv[t] = g_logv[b * 512 + t];
    __syncthreads();

    float acc = 0.f;
    if (t < 256) {
        const __half2* Kb2 = (const __half2*)(g_Kh + (size_t)b * 512 * 512);
        float v0 = sv[2 * t], v1 = sv[2 * t + 1];
        for (int i = 0; i < 512; i++) {
            float lu = g_logu[b * 512 + i];            // uniform -> broadcast
            float2 k = __half22float2(Kb2[(size_t)i * 256 + t]);
            acc += k.x * k.x * __expf(lu + k.x + v0)
                 + k.y * k.y * __expf(lu + k.y + v1);
        }
    }

    red[t] = acc;
    __syncthreads();
    for (int o = 256; o; o >>= 1) {
        if (t < o) red[t] += red[t + o];
        __syncthreads();
    }
    if (t == 0) out[b] += (EPSV * EPSV) * red[0];
}

// ---------------------------------------------------------------------------
extern "C" void kernel_launch(void* const* d_in, const int* in_sizes, int n_in,
                              void* d_out, int out_size)
{
    const float* a_mask = (const float*)d_in[0];
    const float* pc_a   = (const float*)d_in[1];
    const float* b_mask = (const float*)d_in[2];
    const float* pc_b   = (const float*)d_in[3];
    float* out = (float*)d_out;

    prep_kernel<<<Bb, 512>>>(a_mask, pc_a, b_mask, pc_b, out);
    computeK_kernel<<<dim3(Mm / 32, Nn / 32, Bb), dim3(32, 32)>>>(a_mask, pc_a, b_mask, pc_b);
    sinkhorn_kernel<<<NBLK, NTHR>>>();
    final_kernel<<<Bb, 512>>>(out);
}

// round 5
// speedup vs baseline: 1.8221x; 1.6701x over previous
#include <cuda_runtime.h>
#include <math.h>

#define Bb 32
#define Nn 512
#define Mm 512
#define EPSV 0.05f
#define NITERS 50

#define NBLK 128            // 4 blocks per batch, 1 per SM
#define NTHR 1024           // 32 warps, warp owns 4 rows
#define CACHE_ROWS 80       // rows of eK slice cached in SMEM per block

// Scratch (device globals: allocation-free per harness rules)
__device__ float g_eK  [(size_t)Bb * Nn * Mm];  // exp(logK), row-major [b][i][j]
__device__ float g_ahat[Bb * Nn];               // normalized masked weights
__device__ float g_bhat[Bb * Mm];
__device__ float g_uhat[Bb * Nn];               // final u-scalings
__device__ float g_Spart[2][Bb][4][Mm];         // column-sum partials (dbl-buffered)
__device__ float g_fpart[Bb * 8];               // final ot partials

// per-batch software barrier
__device__ unsigned g_count[Bb];
__device__ volatile unsigned g_gen[Bb];

// ---------------------------------------------------------------------------
// prep: normalized weights, huber into out[b], barrier reset. grid=B, block=512
__global__ void prep_kernel(const float* __restrict__ a_mask,
                            const float* __restrict__ pc_a,
                            const float* __restrict__ b_mask,
                            const float* __restrict__ pc_b,
                            float* __restrict__ out)
{
    int b = blockIdx.x, t = threadIdx.x;
    if (t == 0) { g_count[b] = 0; g_gen[b] = 0; }

    float apt = a_mask[b * Nn + t] * pc_a[(b * Nn + t) * 3 + 2];
    float bpt = b_mask[b * Mm + t] * pc_b[(b * Mm + t) * 3 + 2];

    __shared__ float ra[512], rb[512];
    ra[t] = apt; rb[t] = bpt;
    __syncthreads();
    for (int o = 256; o; o >>= 1) {
        if (t < o) { ra[t] += ra[t + o]; rb[t] += rb[t + o]; }
        __syncthreads();
    }
    float sa = ra[0], sb = rb[0];

    g_ahat[b * Nn + t] = apt / sa;   // masked -> 0 naturally
    g_bhat[b * Mm + t] = bpt / sb;

    if (t == 0) {
        float e = sa - sb;
        float ae = fabsf(e);
        out[b] = (ae <= 1.f) ? 0.5f * e * e : (ae - 0.5f);
    }
}

// ---------------------------------------------------------------------------
// eK = exp(-d/eps) for valid pairs, 1.0 for masked (logK=0 in reference).
// grid = (M/32, N/32, B), block = (32,32)
__global__ void computeEK_kernel(const float* __restrict__ a_mask,
                                 const float* __restrict__ pc_a,
                                 const float* __restrict__ b_mask,
                                 const float* __restrict__ pc_b)
{
    int b  = blockIdx.z;
    int i0 = blockIdx.y * 32, j0 = blockIdx.x * 32;
    int tx = threadIdx.x, ty = threadIdx.y;

    __shared__ float ax[32], ay[32], av[32];
    __shared__ float bx[32], by[32], bv[32];

    if (ty == 0) {
        int i = i0 + tx; int base = (b * Nn + i) * 3;
        ax[tx] = pc_a[base + 0];
        ay[tx] = pc_a[base + 1];
        av[tx] = (a_mask[b * Nn + i] * pc_a[base + 2] > 0.f) ? 1.f : 0.f;
    } else if (ty == 1) {
        int j = j0 + tx; int base = (b * Mm + j) * 3;
        bx[tx] = pc_b[base + 0];
        by[tx] = pc_b[base + 1];
        bv[tx] = (b_mask[b * Mm + j] * pc_b[base + 2] > 0.f) ? 1.f : 0.f;
    }
    __syncthreads();

    float dx = ax[ty] - bx[tx];
    float dy = ay[ty] - by[tx];
    float d  = sqrtf(dx * dx + dy * dy + 1e-12f);
    float val = (av[ty] * bv[tx] > 0.f) ? __expf(-d * (1.f / EPSV)) : 1.f;

    g_eK[((size_t)(b * Nn + (i0 + ty))) * Mm + (j0 + tx)] = val;
}

// ---------------------------------------------------------------------------
// per-batch grid barrier (4 blocks of one batch)
__device__ __forceinline__ void gsync_batch(int b, unsigned target)
{
    __syncthreads();
    if (threadIdx.x == 0) {
        __threadfence();
        unsigned arrived = atomicAdd(&g_count[b], 1u);
        if (arrived == 3u) {
            g_count[b] = 0;
            __threadfence();
            g_gen[b] = target;
        } else {
            while (g_gen[b] < target) { }
        }
    }
    __syncthreads();
}

// ---------------------------------------------------------------------------
// fused multiplicative Sinkhorn: per iteration, one pass over eK computes
// both u-scalings (row sums with old ev) and column partials (with new u).
// grid = NBLK(128), block = NTHR(1024). Block bid: rows [(bid&3)*128, +128)
// of batch bid>>2. Dynamic smem: ev[512] | cpart[32][512] | cache[80][512].
__global__ void __launch_bounds__(NTHR, 1) sinkhorn_kernel()
{
    extern __shared__ float smem[];
    float* ev    = smem;               // 512
    float* cpart = smem + 512;         // 32*512
    float* cache = smem + 512 + 32 * 512;  // CACHE_ROWS*512

    int batch    = blockIdx.x >> 2;
    int slot     = blockIdx.x & 3;
    int row_base = slot * 128;
    int t    = threadIdx.x;
    int w    = t >> 5, lane = t & 31;

    const float* eK_slice = g_eK + ((size_t)(batch * 512 + row_base)) * 512;

    // fill SMEM cache with first CACHE_ROWS rows of this block's slice
    {
        const float4* src = (const float4*)eK_slice;
        float4* dst = (float4*)cache;
        for (int k = t; k < CACHE_ROWS * 128; k += NTHR) dst[k] = src[k];
    }

    // preload b_hat for ev computation (constant)
    float bh = (t < 512) ? g_bhat[batch * 512 + t] : 0.f;
    __syncthreads();

    for (int it = 0; it < NITERS; ++it) {
        // ---- ev[j] = exp(logv_{it-1}) ----
        if (t < 512) {
            if (it == 0) {
                ev[t] = 1.f;   // reference starts logv = 0 (incl. masked cols)
            } else {
                int rb = it & 1;
                float S = __ldcg(&g_Spart[rb][batch][0][t])
                        + __ldcg(&g_Spart[rb][batch][1][t])
                        + __ldcg(&g_Spart[rb][batch][2][t])
                        + __ldcg(&g_Spart[rb][batch][3][t]);
                ev[t] = bh / fmaxf(S, 1e-35f);   // masked: bh=0 -> ev=0
            }
        }
        __syncthreads();

        // hoist this lane's 16 ev values into registers
        const float4* ev4 = (const float4*)ev;
        float4 e0 = ev4[lane * 2], e1 = ev4[lane * 2 + 1];
        float4 e2 = ev4[64 + lane * 2], e3 = ev4[64 + lane * 2 + 1];
        float sv[16] = {e0.x,e0.y,e0.z,e0.w, e1.x,e1.y,e1.z,e1.w,
                        e2.x,e2.y,e2.z,e2.w, e3.x,e3.y,e3.z,e3.w};

        float c[16];
#pragma unroll
        for (int k = 0; k < 16; k++) c[k] = 0.f;

#pragma unroll
        for (int r = 0; r < 4; r++) {
            int l = w * 4 + r;                 // local row 0..127
            const float4* src = (l < CACHE_ROWS)
                ? (const float4*)(cache + l * 512)
                : (const float4*)(eK_slice + (size_t)l * 512);
            float4 a0 = src[lane * 2], a1 = src[lane * 2 + 1];
            float4 a2 = src[64 + lane * 2], a3 = src[64 + lane * 2 + 1];
            float x[16] = {a0.x,a0.y,a0.z,a0.w, a1.x,a1.y,a1.z,a1.w,
                           a2.x,a2.y,a2.z,a2.w, a3.x,a3.y,a3.z,a3.w};

            float s = 0.f;
#pragma unroll
            for (int k = 0; k < 16; k++) s = fmaf(x[k], sv[k], s);
#pragma unroll
            for (int o = 16; o; o >>= 1) s += __shfl_xor_sync(0xFFFFFFFFu, s, o);
            s = fmaxf(s, 1e-35f);

            float ah = g_ahat[batch * 512 + row_base + l];   // uniform
            float uh = __fdividef(ah, s);                    // exp(logu_it)

            if (it == NITERS - 1 && lane == 0)
                g_uhat[batch * 512 + row_base + l] = uh;

#pragma unroll
            for (int k = 0; k < 16; k++) c[k] = fmaf(x[k], uh, c[k]);
        }

        // write per-warp column partials
        float4* cp = (float4*)(cpart + w * 512);
        cp[lane * 2]      = make_float4(c[0], c[1], c[2], c[3]);
        cp[lane * 2 + 1]  = make_float4(c[4], c[5], c[6], c[7]);
        cp[64 + lane * 2] = make_float4(c[8], c[9], c[10], c[11]);
        cp[65 + lane * 2] = make_float4(c[12], c[13], c[14], c[15]);
        __syncthreads();

        // reduce 32 warps -> this block's column-sum partial
        if (t < 512) {
            float s = 0.f;
#pragma unroll
            for (int w2 = 0; w2 < 32; w2++) s += cpart[w2 * 512 + t];
            g_Spart[(it + 1) & 1][batch][slot][t] = s;
        }

        if (it < NITERS - 1) gsync_batch(batch, (unsigned)(it + 1));
    }
}

// ---------------------------------------------------------------------------
// finalA: partial ot sums. grid = (8 slots, B), block = 256.
// ot = sum_ij d^2 * flow, d = -eps*ln(eK), flow = uhat*eK*ev (masked -> 0)
__global__ void finalA_kernel()
{
    __shared__ float ev[512];
    __shared__ float red[8];
    int b = blockIdx.y, slot = blockIdx.x;
    int t = threadIdx.x, w = t >> 5, lane = t & 31;

    for (int j = t; j < 512; j += 256) {
        float S = g_Spart[0][b][0][j] + g_Spart[0][b][1][j]
                + g_Spart[0][b][2][j] + g_Spart[0][b][3][j];
        ev[j] = g_bhat[b * 512 + j] / fmaxf(S, 1e-35f);
    }
    __syncthreads();

    const float4* ev4 = (const float4*)ev;
    float4 e0 = ev4[lane * 2], e1 = ev4[lane * 2 + 1];
    float4 e2 = ev4[64 + lane * 2], e3 = ev4[64 + lane * 2 + 1];
    float sv[16] = {e0.x,e0.y,e0.z,e0.w, e1.x,e1.y,e1.z,e1.w,
                    e2.x,e2.y,e2.z,e2.w, e3.x,e3.y,e3.z,e3.w};

    float acc = 0.f;
#pragma unroll
    for (int r = 0; r < 8; r++) {
        int i = slot * 64 + w * 8 + r;
        const float4* src = (const float4*)(g_eK + ((size_t)(b * 512 + i)) * 512);
        float uh = g_uhat[b * 512 + i];
        float4 a0 = src[lane * 2], a1 = src[lane * 2 + 1];
        float4 a2 = src[64 + lane * 2], a3 = src[64 + lane * 2 + 1];
        float x[16] = {a0.x,a0.y,a0.z,a0.w, a1.x,a1.y,a1.z,a1.w,
                       a2.x,a2.y,a2.z,a2.w, a3.x,a3.y,a3.z,a3.w};
#pragma unroll
        for (int k = 0; k < 16; k++) {
            float e = x[k];
            if (e > 0.f) {
                float lk = __logf(e);            // = logK (masked: e=1 -> 0)
                acc += lk * lk * e * uh * sv[k];
            }
        }
    }

#pragma unroll
    for (int o = 16; o; o >>= 1) acc += __shfl_xor_sync(0xFFFFFFFFu, acc, o);
    if (lane == 0) red[w] = acc;
    __syncthreads();
    if (t == 0) {
        float s = 0.f;
#pragma unroll
        for (int k = 0; k < 8; k++) s += red[k];
        g_fpart[b * 8 + slot] = s;
    }
}

// finalB: out[b] += eps^2 * sum of 8 partials. grid = B, block = 32
__global__ void finalB_kernel(float* __restrict__ out)
{
    int b = blockIdx.x;
    if (threadIdx.x == 0) {
        float s = 0.f;
#pragma unroll
        for (int k = 0; k < 8; k++) s += g_fpart[b * 8 + k];
        out[b] += (EPSV * EPSV) * s;
    }
}

// ---------------------------------------------------------------------------
extern "C" void kernel_launch(void* const* d_in, const int* in_sizes, int n_in,
                              void* d_out, int out_size)
{
    const float* a_mask = (const float*)d_in[0];
    const float* pc_a   = (const float*)d_in[1];
    const float* b_mask = (const float*)d_in[2];
    const float* pc_b   = (const float*)d_in[3];
    float* out = (float*)d_out;

    static const int SMEM_BYTES = (512 + 32 * 512 + CACHE_ROWS * 512) * 4;
    cudaFuncSetAttribute(sinkhorn_kernel,
                         cudaFuncAttributeMaxDynamicSharedMemorySize, SMEM_BYTES);

    prep_kernel<<<Bb, 512>>>(a_mask, pc_a, b_mask, pc_b, out);
    computeEK_kernel<<<dim3(Mm / 32, Nn / 32, Bb), dim3(32, 32)>>>(a_mask, pc_a, b_mask, pc_b);
    sinkhorn_kernel<<<NBLK, NTHR, SMEM_BYTES>>>();
    finalA_kernel<<<dim3(8, Bb), 256>>>();
    finalB_kernel<<<Bb, 32>>>(out);
}

// round 8
// speedup vs baseline: 2.6801x; 1.4709x over previous
#include <cuda_runtime.h>
#include <cuda_fp16.h>
#include <math.h>

#define Bb 32
#define Nn 512
#define Mm 512
#define EPSV 0.05f
#define INV_EPS 20.0f
#define SHIFT 10.0f
#define NITERS 50

#define NBLK 128            // 4 blocks per batch, 1 per SM
#define NTHR 512            // 16 warps, warp owns 8 rows

// Scratch (device globals: allocation-free per harness rules)
__device__ float g_ahat[Bb * Nn];               // normalized masked weights
__device__ float g_bhat[Bb * Mm];
__device__ float g_uhat[Bb * Nn];               // final scaled u' = u*e^{-20dmin-SHIFT}
__device__ float g_dmin[Bb * Nn];               // per-row min valid distance
__device__ float g_mmask[Bb];                   // # masked columns per batch
__device__ float g_Spart[2][Bb][4][Mm];         // column-sum partials (dbl-buffered)
__device__ float g_fpart[Bb * 8];               // final ot partials

// per-batch software barrier
__device__ unsigned g_count[Bb];
__device__ volatile unsigned g_gen[Bb];

// ---------------------------------------------------------------------------
// prep: normalized weights, masked-col count, huber into out[b], barrier reset
__global__ void prep_kernel(const float* __restrict__ a_mask,
                            const float* __restrict__ pc_a,
                            const float* __restrict__ b_mask,
                            const float* __restrict__ pc_b,
                            float* __restrict__ out)
{
    int b = blockIdx.x, t = threadIdx.x;
    if (t == 0) { g_count[b] = 0; g_gen[b] = 0; }

    float apt = a_mask[b * Nn + t] * pc_a[(b * Nn + t) * 3 + 2];
    float bpt = b_mask[b * Mm + t] * pc_b[(b * Mm + t) * 3 + 2];

    __shared__ float ra[512], rb[512];
    ra[t] = apt; rb[t] = bpt;
    __syncthreads();
    for (int o = 256; o; o >>= 1) {
        if (t < o) { ra[t] += ra[t + o]; rb[t] += rb[t + o]; }
        __syncthreads();
    }
    float sa = ra[0], sb = rb[0];
    __syncthreads();

    g_ahat[b * Nn + t] = apt / sa;   // masked -> 0
    g_bhat[b * Mm + t] = bpt / sb;

    // count masked b columns
    ra[t] = (bpt > 0.f) ? 0.f : 1.f;
    __syncthreads();
    for (int o = 256; o; o >>= 1) {
        if (t < o) ra[t] += ra[t + o];
        __syncthreads();
    }
    if (t == 0) {
        g_mmask[b] = ra[0];
        float e = sa - sb;
        float ae = fabsf(e);
        out[b] = (ae <= 1.f) ? 0.5f * e * e : (ae - 0.5f);
    }
}

// ---------------------------------------------------------------------------
// per-batch grid barrier (4 blocks of one batch)
__device__ __forceinline__ void gsync_batch(int b, unsigned target)
{
    __syncthreads();
    if (threadIdx.x == 0) {
        __threadfence();
        unsigned arrived = atomicAdd(&g_count[b], 1u);
        if (arrived == 3u) {
            g_count[b] = 0;
            __threadfence();
            g_gen[b] = target;
        } else {
            while (g_gen[b] < target) { }
        }
    }
    __syncthreads();
}

// ---------------------------------------------------------------------------
// persistent fused Sinkhorn, SMEM-resident fp16 tile with row-max scaling:
//   t_ij = exp((dmin_i - d_ij)*INV_EPS + SHIFT)   (0 for masked pairs)
// grid = NBLK(128), block = NTHR(512). Block: rows [(bid&3)*128, +128) of
// batch bid>>2. smem: ev[512] | cpart[16*512] | tile half[128*512].
__global__ void __launch_bounds__(NTHR, 1) sinkhorn_kernel(
    const float* __restrict__ pc_a, const float* __restrict__ pc_b)
{
    extern __shared__ float smem[];
    float*  ev    = smem;                       // 512 f
    float*  cpart = smem + 512;                 // 16*512 f
    __half* tile  = (__half*)(smem + 512 + 16 * 512);   // 128*512 h

    int batch    = blockIdx.x >> 2;
    int slot     = blockIdx.x & 3;
    int row_base = slot * 128;
    int t = threadIdx.x, w = t >> 5, lane = t & 31;

    // ---- build tile ---- (temporary overlay of pc_b columns in cpart space)
    float* bxs = cpart;
    float* bys = cpart + 512;
    float* bvs = cpart + 1024;
    for (int j = t; j < 512; j += NTHR) {
        int gb = batch * 512 + j;
        bxs[j] = pc_b[gb * 3 + 0];
        bys[j] = pc_b[gb * 3 + 1];
        bvs[j] = g_bhat[gb];                    // >0 iff valid column
    }
    __syncthreads();

    float mmask = g_mmask[batch];
    float scr[8], ahr[8];
#pragma unroll
    for (int r = 0; r < 8; r++) {
        int row  = w * 8 + r;
        int grow = batch * 512 + row_base + row;
        float ax = pc_a[grow * 3 + 0];          // broadcast
        float ay = pc_a[grow * 3 + 1];
        float ah = g_ahat[grow];
        ahr[r] = ah;

        float dv[16];
        float mn = 1e30f;
#pragma unroll
        for (int k = 0; k < 16; k++) {
            int j = k * 32 + lane;
            float dx = ax - bxs[j], dy = ay - bys[j];
            float d  = sqrtf(__fmaf_rn(dx, dx, __fmaf_rn(dy, dy, 1e-12f)));
            dv[k] = d;
            if (bvs[j] > 0.f) mn = fminf(mn, d);
        }
#pragma unroll
        for (int o = 16; o; o >>= 1) mn = fminf(mn, __shfl_xor_sync(0xFFFFFFFFu, mn, o));

        if (lane == 0) g_dmin[grow] = mn;
        scr[r] = __expf(-__fmaf_rn(INV_EPS, mn, SHIFT));   // e^{-20*mn-SHIFT}

#pragma unroll
        for (int k = 0; k < 16; k++) {
            int j = k * 32 + lane;
            float arg = fminf((mn - dv[k]) * INV_EPS, 0.f) + SHIFT;
            float tv  = (bvs[j] > 0.f && ah > 0.f) ? __expf(arg) : 0.f;
            tile[row * 512 + j] = __float2half(tv);
        }
    }

    float bh = g_bhat[batch * 512 + t];
    __syncthreads();     // cpart overlay dead; tile per-warp self-owned

    // ---- 50 iterations ----
    for (int it = 0; it < NITERS; ++it) {
        if (it == 0) {
            ev[t] = 1.f;                        // reference: logv starts at 0
        } else {
            int rb = it & 1;
            float S = __ldcg(&g_Spart[rb][batch][0][t])
                    + __ldcg(&g_Spart[rb][batch][1][t])
                    + __ldcg(&g_Spart[rb][batch][2][t])
                    + __ldcg(&g_Spart[rb][batch][3][t]);
            ev[t] = bh / fmaxf(S, 1e-35f);      // masked: bh=0 -> ev=0
        }
        __syncthreads();

        const float4* ev4 = (const float4*)ev;
        float4 e0 = ev4[lane * 2],      e1 = ev4[lane * 2 + 1];
        float4 e2 = ev4[64 + lane * 2], e3 = ev4[64 + lane * 2 + 1];
        float sv[16] = {e0.x,e0.y,e0.z,e0.w, e1.x,e1.y,e1.z,e1.w,
                        e2.x,e2.y,e2.z,e2.w, e3.x,e3.y,e3.z,e3.w};

        float c[16];
#pragma unroll
        for (int k = 0; k < 16; k++) c[k] = 0.f;

#pragma unroll
        for (int r = 0; r < 8; r++) {
            int row = w * 8 + r;
            const uint4* rp = (const uint4*)(tile + row * 512);
            uint4 q0 = rp[lane], q1 = rp[32 + lane];

            float x[16];
            {
                float2 p;
                p = __half22float2(*(const __half2*)&q0.x); x[0]=p.x;  x[1]=p.y;
                p = __half22float2(*(const __half2*)&q0.y); x[2]=p.x;  x[3]=p.y;
                p = __half22float2(*(const __half2*)&q0.z); x[4]=p.x;  x[5]=p.y;
                p = __half22float2(*(const __half2*)&q0.w); x[6]=p.x;  x[7]=p.y;
                p = __half22float2(*(const __half2*)&q1.x); x[8]=p.x;  x[9]=p.y;
                p = __half22float2(*(const __half2*)&q1.y); x[10]=p.x; x[11]=p.y;
                p = __half22float2(*(const __half2*)&q1.z); x[12]=p.x; x[13]=p.y;
                p = __half22float2(*(const __half2*)&q1.w); x[14]=p.x; x[15]=p.y;
            }

            float dot = 0.f;
#pragma unroll
            for (int k = 0; k < 16; k++) dot = __fmaf_rn(x[k], sv[k], dot);
#pragma unroll
            for (int o = 16; o; o >>= 1) dot += __shfl_xor_sync(0xFFFFFFFFu, dot, o);

            float uhp;
            if (it == 0) {
                // unscaled denominator: dot*sc + Mmask (overflow-proof)
                float den = __fmaf_rn(dot, scr[r], mmask);
                uhp = __fdividef(ahr[r] * scr[r], fmaxf(den, 1e-35f));
            } else {
                uhp = __fdividef(ahr[r], fmaxf(dot, 1e-35f));
            }

            if (it == NITERS - 1 && lane == 0)
                g_uhat[batch * 512 + row_base + row] = uhp;

#pragma unroll
            for (int k = 0; k < 16; k++) c[k] = __fmaf_rn(x[k], uhp, c[k]);
        }

        // per-warp column partials -> smem
        float4* cp = (float4*)(cpart + w * 512);
        cp[lane * 2]      = make_float4(c[0],  c[1],  c[2],  c[3]);
        cp[lane * 2 + 1]  = make_float4(c[4],  c[5],  c[6],  c[7]);
        cp[64 + lane * 2] = make_float4(c[8],  c[9],  c[10], c[11]);
        cp[65 + lane * 2] = make_float4(c[12], c[13], c[14], c[15]);
        __syncthreads();

        float s = 0.f;
#pragma unroll
        for (int w2 = 0; w2 < 16; w2++) s += cpart[w2 * 512 + t];
        g_Spart[(it + 1) & 1][batch][slot][t] = s;

        if (it < NITERS - 1) gsync_batch(batch, (unsigned)(it + 1));
    }
}

// ---------------------------------------------------------------------------
// finalA: ot partials. flow = uhat * fp16(t) * ev  (identical t expression as
// tile build -> self-consistent).  grid=(8,B), block=256
__global__ void finalA_kernel(const float* __restrict__ pc_a,
                              const float* __restrict__ pc_b)
{
    __shared__ float ev[512], bxs[512], bys[512];
    __shared__ float red[8];
    int b = blockIdx.y, slot = blockIdx.x;
    int t = threadIdx.x, w = t >> 5, lane = t & 31;

    for (int j = t; j < 512; j += 256) {
        float S = g_Spart[0][b][0][j] + g_Spart[0][b][1][j]
                + g_Spart[0][b][2][j] + g_Spart[0][b][3][j];
        ev[j]  = g_bhat[b * 512 + j] / fmaxf(S, 1e-35f);
        bxs[j] = pc_b[(b * 512 + j) * 3 + 0];
        bys[j] = pc_b[(b * 512 + j) * 3 + 1];
    }
    __syncthreads();

    float acc = 0.f;
    for (int r = 0; r < 64; r++) {
        int g = b * 512 + slot * 64 + r;
        float uh = g_uhat[g];                    // broadcast, warp-uniform
        if (uh != 0.f) {
            float ax = pc_a[g * 3 + 0], ay = pc_a[g * 3 + 1];
            float dm = g_dmin[g];
#pragma unroll
            for (int h = 0; h < 2; h++) {
                int j = h * 256 + t;
                float dx = ax - bxs[j], dy = ay - bys[j];
                float d  = sqrtf(__fmaf_rn(dx, dx, __fmaf_rn(dy, dy, 1e-12f)));
                float arg = fminf((dm - d) * INV_EPS, 0.f) + SHIFT;
                float tq  = __half2float(__float2half(__expf(arg)));
                acc = __fmaf_rn(d * d, (uh * tq) * ev[j], acc);
            }
        }
    }

#pragma unroll
    for (int o = 16; o; o >>= 1) acc += __shfl_xor_sync(0xFFFFFFFFu, acc, o);
    if (lane == 0) red[w] = acc;
    __syncthreads();
    if (t == 0) {
        float s = 0.f;
#pragma unroll
        for (int k = 0; k < 8; k++) s += red[k];
        g_fpart[b * 8 + slot] = s;
    }
}

// finalB: out[b] += sum of 8 partials (acc already carries d^2 -- NO eps^2!)
__global__ void finalB_kernel(float* __restrict__ out)
{
    int b = blockIdx.x;
    if (threadIdx.x == 0) {
        float s = 0.f;
#pragma unroll
        for (int k = 0; k < 8; k++) s += g_fpart[b * 8 + k];
        out[b] += s;
    }
}

// ---------------------------------------------------------------------------
extern "C" void kernel_launch(void* const* d_in, const int* in_sizes, int n_in,
                              void* d_out, int out_size)
{
    const float* a_mask = (const float*)d_in[0];
    const float* pc_a   = (const float*)d_in[1];
    const float* b_mask = (const float*)d_in[2];
    const float* pc_b   = (const float*)d_in[3];
    float* out = (float*)d_out;

    static const int SMEM_BYTES = (512 + 16 * 512) * 4 + 128 * 512 * 2;  // 162 KB
    cudaFuncSetAttribute(sinkhorn_kernel,
                         cudaFuncAttributeMaxDynamicSharedMemorySize, SMEM_BYTES);

    prep_kernel<<<Bb, 512>>>(a_mask, pc_a, b_mask, pc_b, out);
    sinkhorn_kernel<<<NBLK, NTHR, SMEM_BYTES>>>(pc_a, pc_b);
    finalA_kernel<<<dim3(8, Bb), 256>>>(pc_a, pc_b);
    finalB_kernel<<<Bb, 32>>>(out);
}